// round 4
// baseline (speedup 1.0000x reference)
#include <cuda_runtime.h>
#include <stdint.h>

// MoE EP-combine: out[token_indices[r]] += sorted_gates[r] * expert_outputs[r]
// Inputs (metadata order):
//   d_in[0] output_buffer  f32 [16384, 2048]  (zeros; ignored)
//   d_in[1] expert_outputs f32 [32768, 2048]
//   d_in[2] sorted_gates   f32 [32768]
//   d_in[3] token_indices  int (dtype detected at runtime: i32 or i64) [32768]
// Output: f32 [16384, 2048]

#define NUM_TOKENS 16384
#define NUM_SEL    32768
#define D_MODEL    2048
#define D_VEC4     (D_MODEL / 4)      // 512 float4 per row
#define MAX_CONTRIB 32

__device__ int   g_cnt[NUM_TOKENS];
__device__ int   g_rows[NUM_TOKENS * MAX_CONTRIB];
__device__ float g_gate[NUM_TOKENS * MAX_CONTRIB];
__device__ int   g_idx_is_i64;

// Detect index dtype. If the buffer is genuine int64, every 8-byte word is a
// token id < NUM_TOKENS. If it is int32, the high 32 bits of each 8-byte word
// hold another random token id, so w >= NUM_TOKENS with prob ~1 per sample.
__global__ void detect_idx_dtype_kernel(const unsigned long long* __restrict__ p) {
    int is64 = 1;
    #pragma unroll
    for (int i = 0; i < 8; ++i) {
        if (p[i] >= (unsigned long long)NUM_TOKENS) { is64 = 0; }
    }
    g_idx_is_i64 = is64;
}

__global__ void zero_counts_kernel() {
    int i = blockIdx.x * blockDim.x + threadIdx.x;
    if (i < NUM_TOKENS) g_cnt[i] = 0;
}

__global__ void scatter_kernel(const void* __restrict__ token_indices,
                               const float* __restrict__ gates) {
    int r = blockIdx.x * blockDim.x + threadIdx.x;
    if (r >= NUM_SEL) return;
    int t;
    if (g_idx_is_i64) {
        t = (int)((const long long*)token_indices)[r];
    } else {
        t = ((const int*)token_indices)[r];
    }
    float g = gates[r];
    int slot = atomicAdd(&g_cnt[t], 1);
    if (slot < MAX_CONTRIB) {
        g_rows[t * MAX_CONTRIB + slot] = r;
        g_gate[t * MAX_CONTRIB + slot] = g;
    }
}

// One CTA (256 threads) per token row. Each thread owns 2 float4 slots (32 B).
__global__ void __launch_bounds__(256) combine_kernel(
    const float4* __restrict__ expert,   // [NUM_SEL, D_VEC4]
    float4* __restrict__ out)            // [NUM_TOKENS, D_VEC4]
{
    int t = blockIdx.x;
    int c = g_cnt[t];
    if (c > MAX_CONTRIB) c = MAX_CONTRIB;

    int i0 = threadIdx.x;            // float4 index 0..255
    int i1 = threadIdx.x + 256;      // float4 index 256..511

    float4 acc0 = make_float4(0.f, 0.f, 0.f, 0.f);
    float4 acc1 = make_float4(0.f, 0.f, 0.f, 0.f);

    const int base = t * MAX_CONTRIB;
    for (int j = 0; j < c; ++j) {
        int   r = g_rows[base + j];
        float g = g_gate[base + j];
        const float4* e = expert + (size_t)r * D_VEC4;
        float4 v0 = e[i0];
        float4 v1 = e[i1];
        acc0.x += g * v0.x; acc0.y += g * v0.y;
        acc0.z += g * v0.z; acc0.w += g * v0.w;
        acc1.x += g * v1.x; acc1.y += g * v1.y;
        acc1.z += g * v1.z; acc1.w += g * v1.w;
    }

    float4* o = out + (size_t)t * D_VEC4;
    o[i0] = acc0;
    o[i1] = acc1;
}

extern "C" void kernel_launch(void* const* d_in, const int* in_sizes, int n_in,
                              void* d_out, int out_size)
{
    const float* expert = (const float*)d_in[1];
    const float* gates  = (const float*)d_in[2];
    const void*  tidx   = d_in[3];
    float*       out    = (float*)d_out;

    detect_idx_dtype_kernel<<<1, 1>>>((const unsigned long long*)tidx);
    zero_counts_kernel<<<(NUM_TOKENS + 255) / 256, 256>>>();
    scatter_kernel<<<(NUM_SEL + 255) / 256, 256>>>(tidx, gates);
    combine_kernel<<<NUM_TOKENS, 256>>>((const float4*)expert, (float4*)out);
}

// round 8
// speedup vs baseline: 1.0306x; 1.0306x over previous
#include <cuda_runtime.h>
#include <stdint.h>

// MoE EP-combine: out[token_indices[r]] += sorted_gates[r] * expert_outputs[r]
// Inputs (metadata order):
//   d_in[0] output_buffer  f32 [16384, 2048]  (zeros; ignored)
//   d_in[1] expert_outputs f32 [32768, 2048]
//   d_in[2] sorted_gates   f32 [32768]
//   d_in[3] token_indices  (i32 or i64, runtime-detected) [32768]
// Output: f32 [16384, 2048]

#define NUM_TOKENS 16384
#define NUM_SEL    32768
#define D_MODEL    2048
#define D_VEC4     (D_MODEL / 4)      // 512 float4 per row
#define MAX_CONTRIB 32

__device__ int   g_cnt[NUM_TOKENS];
__device__ int   g_rows[NUM_TOKENS * MAX_CONTRIB];
__device__ float g_gate[NUM_TOKENS * MAX_CONTRIB];
__device__ int   g_idx_is_i64;

// Zero counters; thread 0 also probes the index dtype.
// If genuine int64, every 8-byte word is a token id < NUM_TOKENS. If int32,
// the high 32 bits of a word hold another random token id -> >= NUM_TOKENS
// with prob ~1 over 8 samples.
__global__ void zero_and_detect_kernel(const unsigned long long* __restrict__ p) {
    int i = blockIdx.x * blockDim.x + threadIdx.x;
    if (i < NUM_TOKENS) g_cnt[i] = 0;
    if (i == 0) {
        int is64 = 1;
        #pragma unroll
        for (int k = 0; k < 8; ++k)
            if (p[k] >= (unsigned long long)NUM_TOKENS) is64 = 0;
        g_idx_is_i64 = is64;
    }
}

__global__ void scatter_kernel(const void* __restrict__ token_indices,
                               const float* __restrict__ gates) {
    int r = blockIdx.x * blockDim.x + threadIdx.x;
    if (r >= NUM_SEL) return;
    int t;
    if (g_idx_is_i64) {
        t = (int)((const long long*)token_indices)[r];
    } else {
        t = ((const int*)token_indices)[r];
    }
    float g = gates[r];
    int slot = atomicAdd(&g_cnt[t], 1);
    if (slot < MAX_CONTRIB) {
        g_rows[t * MAX_CONTRIB + slot] = r;
        g_gate[t * MAX_CONTRIB + slot] = g;
    }
}

__device__ __forceinline__ void fma4(float4& a, float g, const float4& v) {
    a.x += g * v.x; a.y += g * v.y; a.z += g * v.z; a.w += g * v.w;
}

// One CTA (256 threads) per token row. Each thread owns 2 float4 slots (32 B).
// Contributor loop unrolled by 2: the dominant case (c == 2, TOP_K) runs a
// single iteration with 4 independent 16B loads in flight per thread.
__global__ void __launch_bounds__(256) combine_kernel(
    const float4* __restrict__ expert,   // [NUM_SEL, D_VEC4]
    float4* __restrict__ out)            // [NUM_TOKENS, D_VEC4]
{
    int t = blockIdx.x;
    int c = g_cnt[t];
    if (c > MAX_CONTRIB) c = MAX_CONTRIB;

    const int i0 = threadIdx.x;          // float4 index 0..255
    const int i1 = threadIdx.x + 256;    // float4 index 256..511

    float4 acc0 = make_float4(0.f, 0.f, 0.f, 0.f);
    float4 acc1 = make_float4(0.f, 0.f, 0.f, 0.f);

    const int base = t * MAX_CONTRIB;
    int j = 0;
    for (; j + 2 <= c; j += 2) {
        int   ra = g_rows[base + j];
        int   rb = g_rows[base + j + 1];
        float ga = g_gate[base + j];
        float gb = g_gate[base + j + 1];
        const float4* ea = expert + (size_t)ra * D_VEC4;
        const float4* eb = expert + (size_t)rb * D_VEC4;
        // 4 independent streaming loads in flight
        float4 va0 = __ldcs(ea + i0);
        float4 va1 = __ldcs(ea + i1);
        float4 vb0 = __ldcs(eb + i0);
        float4 vb1 = __ldcs(eb + i1);
        fma4(acc0, ga, va0);
        fma4(acc1, ga, va1);
        fma4(acc0, gb, vb0);
        fma4(acc1, gb, vb1);
    }
    if (j < c) {
        int   r = g_rows[base + j];
        float g = g_gate[base + j];
        const float4* e = expert + (size_t)r * D_VEC4;
        float4 v0 = __ldcs(e + i0);
        float4 v1 = __ldcs(e + i1);
        fma4(acc0, g, v0);
        fma4(acc1, g, v1);
    }

    float4* o = out + (size_t)t * D_VEC4;
    __stcs(o + i0, acc0);   // write-once, bypass-ish L2 residency
    __stcs(o + i1, acc1);
}

extern "C" void kernel_launch(void* const* d_in, const int* in_sizes, int n_in,
                              void* d_out, int out_size)
{
    const float* expert = (const float*)d_in[1];
    const float* gates  = (const float*)d_in[2];
    const void*  tidx   = d_in[3];
    float*       out    = (float*)d_out;

    zero_and_detect_kernel<<<(NUM_TOKENS + 255) / 256, 256>>>(
        (const unsigned long long*)tidx);
    scatter_kernel<<<(NUM_SEL + 255) / 256, 256>>>(tidx, gates);
    combine_kernel<<<NUM_TOKENS, 256>>>((const float4*)expert, (float4*)out);
}

// round 12
// speedup vs baseline: 1.1540x; 1.1197x over previous
#include <cuda_runtime.h>
#include <stdint.h>

// MoE EP-combine: out[token_indices[r]] += sorted_gates[r] * expert_outputs[r]
// Inputs (metadata order):
//   d_in[0] output_buffer  f32 [16384, 2048]  (zeros; ignored)
//   d_in[1] expert_outputs f32 [32768, 2048]
//   d_in[2] sorted_gates   f32 [32768]
//   d_in[3] token_indices  (i32 or i64, runtime-detected) [32768]
// Output: f32 [16384, 2048]
//
// Self-cleaning counters: combine_kernel resets g_cnt[t] to 0 after use, so
// no zeroing pass is needed (globals are zero-init at module load; every
// graph replay leaves cnt back at 0).

#define NUM_TOKENS 16384
#define NUM_SEL    32768
#define D_MODEL    2048
#define D_VEC4     (D_MODEL / 4)      // 512 float4 per row
#define MAX_CONTRIB 32

__device__ int   g_cnt[NUM_TOKENS];
__device__ int   g_rows[NUM_TOKENS * MAX_CONTRIB];
__device__ float g_gate[NUM_TOKENS * MAX_CONTRIB];

// Index-dtype probe: if the buffer is genuine int64, every 8-byte word is a
// token id < NUM_TOKENS. If int32, the high 32 bits of a word hold another
// random token id, so >= NUM_TOKENS over 8 samples with prob ~1.
__device__ __forceinline__ int probe_idx_is_i64(const unsigned long long* p) {
    int is64 = 1;
    #pragma unroll
    for (int k = 0; k < 8; ++k)
        if (p[k] >= (unsigned long long)NUM_TOKENS) is64 = 0;
    return is64;
}

__global__ void __launch_bounds__(256) scatter_kernel(
    const void* __restrict__ token_indices,
    const float* __restrict__ gates)
{
    __shared__ int s_is64;
    if (threadIdx.x == 0)
        s_is64 = probe_idx_is_i64((const unsigned long long*)token_indices);
    __syncthreads();

    int r = blockIdx.x * blockDim.x + threadIdx.x;
    if (r >= NUM_SEL) return;

    int t;
    if (s_is64) t = (int)((const long long*)token_indices)[r];
    else        t = ((const int*)token_indices)[r];

    float g = gates[r];
    int slot = atomicAdd(&g_cnt[t], 1);
    if (slot < MAX_CONTRIB) {
        g_rows[t * MAX_CONTRIB + slot] = r;
        g_gate[t * MAX_CONTRIB + slot] = g;
    }
}

__device__ __forceinline__ void fma4(float4& a, float g, const float4& v) {
    a.x += g * v.x; a.y += g * v.y; a.z += g * v.z; a.w += g * v.w;
}

// One CTA (256 threads) per token. Each thread owns 2 float4 slots (32 B).
// cnt and the first 4 (row, gate) slots are fetched with INDEPENDENT loads
// (vectorized, 128B-aligned) so the metadata latency is one round trip, not
// two; expert-row loads depend only on the rows vector. Slots beyond cnt are
// predicated off before any expert dereference (no wasted bandwidth).
__global__ void __launch_bounds__(256) combine_kernel(
    const float4* __restrict__ expert,   // [NUM_SEL, D_VEC4]
    float4* __restrict__ out)            // [NUM_TOKENS, D_VEC4]
{
    const int t    = blockIdx.x;
    const int base = t * MAX_CONTRIB;

    // Independent metadata loads (issue together):
    int c = g_cnt[t];
    int4   rows4  = *(const int4*)  (g_rows + base);   // slots 0..3
    float4 gates4 = *(const float4*)(g_gate + base);
    if (c > MAX_CONTRIB) c = MAX_CONTRIB;

    const int i0 = threadIdx.x;          // float4 index 0..255
    const int i1 = threadIdx.x + 256;    // float4 index 256..511

    float4 acc0 = make_float4(0.f, 0.f, 0.f, 0.f);
    float4 acc1 = make_float4(0.f, 0.f, 0.f, 0.f);

    // Contributors 0..3 (covers ~95% of tokens fully, c avg = 2)
    if (c > 0) {
        const float4* e = expert + (size_t)rows4.x * D_VEC4;
        float4 v0 = __ldcs(e + i0), v1 = __ldcs(e + i1);
        if (c > 1) {
            const float4* e2 = expert + (size_t)rows4.y * D_VEC4;
            float4 w0 = __ldcs(e2 + i0), w1 = __ldcs(e2 + i1);
            if (c > 2) {
                const float4* e3 = expert + (size_t)rows4.z * D_VEC4;
                float4 x0 = __ldcs(e3 + i0), x1 = __ldcs(e3 + i1);
                if (c > 3) {
                    const float4* e4 = expert + (size_t)rows4.w * D_VEC4;
                    float4 y0 = __ldcs(e4 + i0), y1 = __ldcs(e4 + i1);
                    fma4(acc0, gates4.w, y0); fma4(acc1, gates4.w, y1);
                }
                fma4(acc0, gates4.z, x0); fma4(acc1, gates4.z, x1);
            }
            fma4(acc0, gates4.y, w0); fma4(acc1, gates4.y, w1);
        }
        fma4(acc0, gates4.x, v0); fma4(acc1, gates4.x, v1);
    }

    // Rare tail: c > 4
    for (int j = 4; j < c; ++j) {
        int   r = g_rows[base + j];
        float g = g_gate[base + j];
        const float4* e = expert + (size_t)r * D_VEC4;
        float4 v0 = __ldcs(e + i0), v1 = __ldcs(e + i1);
        fma4(acc0, g, v0); fma4(acc1, g, v1);
    }

    // Self-clean the counter for the next launch / graph replay.
    if (threadIdx.x == 0) g_cnt[t] = 0;

    float4* o = out + (size_t)t * D_VEC4;
    __stcs(o + i0, acc0);
    __stcs(o + i1, acc1);
}

extern "C" void kernel_launch(void* const* d_in, const int* in_sizes, int n_in,
                              void* d_out, int out_size)
{
    const float* expert = (const float*)d_in[1];
    const float* gates  = (const float*)d_in[2];
    const void*  tidx   = d_in[3];
    float*       out    = (float*)d_out;

    scatter_kernel<<<(NUM_SEL + 255) / 256, 256>>>(tidx, gates);
    combine_kernel<<<NUM_TOKENS, 256>>>((const float4*)expert, (float4*)out);
}